// round 8
// baseline (speedup 1.0000x reference)
#include <cuda_runtime.h>
#include <math.h>
#include <stdint.h>

#define DM 256
#define NH 4
#define HD 64
#define NN 768
#define MM 768

#define TILE_M 16
#define NBUF 3
#define NT (MM / TILE_M)              // 48 tiles
#define TILE_BYTES (TILE_M * DM * 4)  // 16384
#define TILE_FLOATS (TILE_M * DM)     // 4096
#define DYN_SMEM_BYTES ((NH * MM + NBUF * TILE_FLOATS) * 4)   // 61440

// av kernel: 3 phases x (64n x 64m attn + 64m x 64c v) floats
#define AV_PHASE_FLOATS (64 * 64 * 2)                          // 8192
#define AV_DYN_BYTES (3 * AV_PHASE_FLOATS * 4)                 // 98304

// ---- scratch (static device globals: allocation-free) ----
__device__ float g_q[NN * DM];
__device__ float g_k[NN * DM];            // k' = 0.125*(xk@Wk.T + bk + bp)
__device__ float g_v[NN * DM];
__device__ float g_R[NN * NH * DM];       // R[n][h][e] = 0.125 * q_h[n] @ Wp_h
__device__ float g_Se[NH * NN * MM];      // q·k' (scaled, bp folded)

// ---- mbarrier / bulk-copy / cp.async PTX helpers ----
__device__ __forceinline__ uint32_t smem_u32(const void* p) {
    return (uint32_t)__cvta_generic_to_shared(p);
}
#define MB_INIT(addr, cnt) \
    asm volatile("mbarrier.init.shared.b64 [%0], %1;" :: "r"(addr), "r"(cnt) : "memory")
#define MB_EXPECT_TX(addr, bytes) \
    asm volatile("mbarrier.arrive.expect_tx.shared.b64 _, [%0], %1;" :: "r"(addr), "r"(bytes) : "memory")
#define MB_ARRIVE(addr) \
    asm volatile("mbarrier.arrive.shared.b64 _, [%0];" :: "r"(addr) : "memory")
#define BULK_G2S(dst, src, bytes, mbar_) \
    asm volatile("cp.async.bulk.shared::cluster.global.mbarrier::complete_tx::bytes [%0], [%1], %2, [%3];" \
                 :: "r"(dst), "l"(src), "r"(bytes), "r"(mbar_) : "memory")

__device__ __forceinline__ void mbar_wait(uint32_t addr, uint32_t parity) {
    asm volatile(
        "{\n\t"
        ".reg .pred P;\n\t"
        "WL%=:\n\t"
        "mbarrier.try_wait.parity.acquire.cta.shared::cta.b64 P, [%0], %1, 0x989680;\n\t"
        "@P bra WD%=;\n\t"
        "bra WL%=;\n\t"
        "WD%=:\n\t"
        "}"
        :: "r"(addr), "r"(parity) : "memory");
}

__device__ __forceinline__ void cp_async16(float* dst, const float* src) {
    asm volatile("cp.async.ca.shared.global [%0], [%1], 16;"
                 :: "r"(smem_u32(dst)), "l"(src) : "memory");
}
#define CP_COMMIT() asm volatile("cp.async.commit_group;" ::: "memory")
#define CP_WAIT(n)  asm volatile("cp.async.wait_group %0;" :: "n"(n) : "memory")

// ============================================================
// K1: q/k'/v projections + fused R projection (z==0 tail)
//     + hidden zero-init (z==2 tail).  grid (48, 3), 256 threads.
// ============================================================
__global__ __launch_bounds__(256) void qkv_kernel(
    const float* __restrict__ in_q, const float* __restrict__ in_k, const float* __restrict__ in_v,
    const float* __restrict__ Wq, const float* __restrict__ bq,
    const float* __restrict__ Wk, const float* __restrict__ bk,
    const float* __restrict__ Wv, const float* __restrict__ bv,
    const float* __restrict__ Wp, const float* __restrict__ bp,
    float* __restrict__ out_h)
{
    const int z  = blockIdx.y;
    const int n0 = blockIdx.x * 16;
    const int d  = threadIdx.x;

    const float* x = (z == 0) ? in_q : ((z == 1) ? in_k : in_v);
    const float* W = (z == 0) ? Wq   : ((z == 1) ? Wk   : Wv);
    float bias     = (z == 0) ? bq[d] : ((z == 1) ? (bk[d] + bp[d]) : bv[d]);
    const float scale = (z == 1) ? 0.125f : 1.0f;
    float* out = (z == 0) ? g_q : ((z == 1) ? g_k : g_v);

    __shared__ float xs[256 * 20];
    for (int idx = d; idx < 16 * 256; idx += 256) {
        int ni = idx >> 8, e = idx & 255;
        xs[e * 20 + ni] = x[(n0 + ni) * DM + e];
    }
    __syncthreads();

    float4 acc[4];
    #pragma unroll
    for (int g = 0; g < 4; g++) acc[g] = make_float4(0.f, 0.f, 0.f, 0.f);

    const float4* Wr = (const float4*)(W + d * DM);
    #pragma unroll 4
    for (int e4 = 0; e4 < 64; e4++) {
        float4 wv = Wr[e4];
        float wa[4] = {wv.x, wv.y, wv.z, wv.w};
        #pragma unroll
        for (int k = 0; k < 4; k++) {
            int e = e4 * 4 + k;
            float w = wa[k];
            #pragma unroll
            for (int g = 0; g < 4; g++) {
                float4 xf = *(const float4*)&xs[e * 20 + g * 4];
                acc[g].x += xf.x * w;
                acc[g].y += xf.y * w;
                acc[g].z += xf.z * w;
                acc[g].w += xf.w * w;
            }
        }
    }
    #pragma unroll
    for (int g = 0; g < 4; g++) {
        out[(n0 + g * 4 + 0) * DM + d] = scale * (acc[g].x + bias);
        out[(n0 + g * 4 + 1) * DM + d] = scale * (acc[g].y + bias);
        out[(n0 + g * 4 + 2) * DM + d] = scale * (acc[g].z + bias);
        out[(n0 + g * 4 + 3) * DM + d] = scale * (acc[g].w + bias);
    }

    // ---- z==2 tail: zero hidden output region (poisoned by harness) ----
    if (z == 2) {
        float4 z4 = make_float4(0.f, 0.f, 0.f, 0.f);
        float4* hp = (float4*)out_h;
        for (int i = blockIdx.x * 256 + d; i < NN * DM / 4; i += 48 * 256)
            hp[i] = z4;
    }

    // ---- z==0 tail: R = 0.125 * q @ Wp (per head) ----
    if (z == 0) {
        __syncthreads();
        #pragma unroll
        for (int g = 0; g < 4; g++) {
            xs[d * 20 + g * 4 + 0] = acc[g].x + bias;
            xs[d * 20 + g * 4 + 1] = acc[g].y + bias;
            xs[d * 20 + g * 4 + 2] = acc[g].z + bias;
            xs[d * 20 + g * 4 + 3] = acc[g].w + bias;
        }
        __syncthreads();

        const int e = d;
        #pragma unroll
        for (int h = 0; h < NH; h++) {
            float4 r0 = make_float4(0.f, 0.f, 0.f, 0.f);
            float4 r1 = make_float4(0.f, 0.f, 0.f, 0.f);
            float4 r2 = make_float4(0.f, 0.f, 0.f, 0.f);
            float4 r3 = make_float4(0.f, 0.f, 0.f, 0.f);
            #pragma unroll 4
            for (int c = 0; c < 64; c++) {
                float w = Wp[(h * 64 + c) * DM + e];
                float4 q0 = *(const float4*)&xs[(h * 64 + c) * 20 + 0];
                float4 q1 = *(const float4*)&xs[(h * 64 + c) * 20 + 4];
                float4 q2 = *(const float4*)&xs[(h * 64 + c) * 20 + 8];
                float4 q3 = *(const float4*)&xs[(h * 64 + c) * 20 + 12];
                r0.x += q0.x * w; r0.y += q0.y * w; r0.z += q0.z * w; r0.w += q0.w * w;
                r1.x += q1.x * w; r1.y += q1.y * w; r1.z += q1.z * w; r1.w += q1.w * w;
                r2.x += q2.x * w; r2.y += q2.y * w; r2.z += q2.z * w; r2.w += q2.w * w;
                r3.x += q3.x * w; r3.y += q3.y * w; r3.z += q3.z * w; r3.w += q3.w * w;
            }
            g_R[(size_t)(n0 +  0) * (NH * DM) + h * DM + e] = 0.125f * r0.x;
            g_R[(size_t)(n0 +  1) * (NH * DM) + h * DM + e] = 0.125f * r0.y;
            g_R[(size_t)(n0 +  2) * (NH * DM) + h * DM + e] = 0.125f * r0.z;
            g_R[(size_t)(n0 +  3) * (NH * DM) + h * DM + e] = 0.125f * r0.w;
            g_R[(size_t)(n0 +  4) * (NH * DM) + h * DM + e] = 0.125f * r1.x;
            g_R[(size_t)(n0 +  5) * (NH * DM) + h * DM + e] = 0.125f * r1.y;
            g_R[(size_t)(n0 +  6) * (NH * DM) + h * DM + e] = 0.125f * r1.z;
            g_R[(size_t)(n0 +  7) * (NH * DM) + h * DM + e] = 0.125f * r1.w;
            g_R[(size_t)(n0 +  8) * (NH * DM) + h * DM + e] = 0.125f * r2.x;
            g_R[(size_t)(n0 +  9) * (NH * DM) + h * DM + e] = 0.125f * r2.y;
            g_R[(size_t)(n0 + 10) * (NH * DM) + h * DM + e] = 0.125f * r2.z;
            g_R[(size_t)(n0 + 11) * (NH * DM) + h * DM + e] = 0.125f * r2.w;
            g_R[(size_t)(n0 + 12) * (NH * DM) + h * DM + e] = 0.125f * r3.x;
            g_R[(size_t)(n0 + 13) * (NH * DM) + h * DM + e] = 0.125f * r3.y;
            g_R[(size_t)(n0 + 14) * (NH * DM) + h * DM + e] = 0.125f * r3.z;
            g_R[(size_t)(n0 + 15) * (NH * DM) + h * DM + e] = 0.125f * r3.w;
        }
    }
}

// ============================================================
// K3: Se[h][n][m] = q_h[n] · k'_h[m].   grid (12, 12, 4), 256 threads.
// ============================================================
__global__ __launch_bounds__(256) void se_kernel()
{
    const int m0 = blockIdx.x * 64;
    const int n0 = blockIdx.y * 64;
    const int h  = blockIdx.z;
    const int tid = threadIdx.x;

    __shared__ float qs[64 * 68];
    __shared__ float ks[64 * 68];
    for (int idx = tid; idx < 64 * 64; idx += 256) {
        int i = idx >> 6, c = idx & 63;
        qs[c * 68 + i] = g_q[(n0 + i) * DM + h * 64 + c];
        ks[c * 68 + i] = g_k[(m0 + i) * DM + h * 64 + c];
    }
    __syncthreads();

    const int tx = tid & 15, ty = tid >> 4;
    float acc[4][4];
    #pragma unroll
    for (int i = 0; i < 4; i++)
        #pragma unroll
        for (int j = 0; j < 4; j++) acc[i][j] = 0.f;

    #pragma unroll 4
    for (int c = 0; c < 64; c++) {
        float4 a = *(const float4*)&qs[c * 68 + ty * 4];
        float4 b = *(const float4*)&ks[c * 68 + tx * 4];
        float av[4] = {a.x, a.y, a.z, a.w};
        float bv[4] = {b.x, b.y, b.z, b.w};
        #pragma unroll
        for (int i = 0; i < 4; i++)
            #pragma unroll
            for (int j = 0; j < 4; j++) acc[i][j] += av[i] * bv[j];
    }
    #pragma unroll
    for (int i = 0; i < 4; i++) {
        float4 r = make_float4(acc[i][0], acc[i][1], acc[i][2], acc[i][3]);
        *(float4*)&g_Se[((size_t)h * NN + (n0 + ty * 4 + i)) * MM + m0 + tx * 4] = r;
    }
}

// ============================================================
// K4: fused RPE-score + softmax, depth-3 bulk-copy pipeline. (unchanged)
// ============================================================
__global__ __launch_bounds__(256, 3) void attn_kernel(const float* __restrict__ emb,
                                                      float* __restrict__ attn_out)
{
    extern __shared__ __align__(16) float dyn[];
    float* sc  = dyn;                 // NH*MM floats (12 KB)
    float* buf = dyn + NH * MM;       // NBUF * 4096 floats (48 KB)

    const int n    = blockIdx.x;
    const int tid  = threadIdx.x;
    const int lane = tid & 31;
    const int wrp  = tid >> 5;

    __shared__ __align__(8) unsigned long long mbar[2 * NBUF];
    __shared__ float red[8];

    const uint32_t mb   = smem_u32(mbar);
    const uint32_t bufa = smem_u32(buf);

    if (tid == 0) {
        #pragma unroll
        for (int i = 0; i < NBUF; i++) {
            MB_INIT(mb + i * 8, 1);
            MB_INIT(mb + (NBUF + i) * 8, 8);
        }
    }

    #pragma unroll
    for (int h = 0; h < NH; h++)
        for (int m = tid; m < MM; m += 256)
            sc[h * MM + m] = g_Se[((size_t)h * NN + n) * MM + m];

    const float4* Rr = (const float4*)(g_R + (size_t)n * NH * DM);
    float4 rA[NH], rB[NH];
    #pragma unroll
    for (int h = 0; h < NH; h++) {
        rA[h] = Rr[h * 64 + lane];
        rB[h] = Rr[h * 64 + 32 + lane];
    }
    __syncthreads();

    const char* src = (const char*)(emb + (size_t)n * MM * DM);
    if (tid == 0) {
        #pragma unroll
        for (int i = 0; i < NBUF; i++) {
            MB_EXPECT_TX(mb + i * 8, TILE_BYTES);
            BULK_G2S(bufa + i * TILE_BYTES, src + (size_t)i * TILE_BYTES,
                     (uint32_t)TILE_BYTES, mb + i * 8);
        }
    }

    const unsigned F = 0xffffffffu;
    const bool o1 = lane & 1, o2 = lane & 2, o4 = lane & 4;

    int s = 0;
    uint32_t par = 0;
    for (int t = 0; t < NT; t++) {
        const uint32_t fa = mb + s * 8;
        const uint32_t ea = mb + (NBUF + s) * 8;

        mbar_wait(fa, par);

        const float* bufp = buf + s * TILE_FLOATS;
        const float4* r0p = (const float4*)(bufp + (wrp * 2) * DM);
        const float4* r1p = (const float4*)(bufp + (wrp * 2 + 1) * DM);
        float4 a0 = r0p[lane], a1 = r0p[32 + lane];
        float4 b0 = r1p[lane], b1 = r1p[32 + lane];

        float acc0[NH], acc1[NH];
        #pragma unroll
        for (int h = 0; h < NH; h++) {
            acc0[h] = a0.x * rA[h].x + a0.y * rA[h].y + a0.z * rA[h].z + a0.w * rA[h].w
                    + a1.x * rB[h].x + a1.y * rB[h].y + a1.z * rB[h].z + a1.w * rB[h].w;
            acc1[h] = b0.x * rA[h].x + b0.y * rA[h].y + b0.z * rA[h].z + b0.w * rA[h].w
                    + b1.x * rB[h].x + b1.y * rB[h].y + b1.z * rB[h].z + b1.w * rB[h].w;
        }

        float sx, rx;
        sx = o1 ? acc0[0] : acc0[1]; rx = __shfl_xor_sync(F, sx, 1);
        float v01a = (o1 ? acc0[1] : acc0[0]) + rx;
        sx = o1 ? acc0[2] : acc0[3]; rx = __shfl_xor_sync(F, sx, 1);
        float v23a = (o1 ? acc0[3] : acc0[2]) + rx;
        sx = o1 ? acc1[0] : acc1[1]; rx = __shfl_xor_sync(F, sx, 1);
        float v01b = (o1 ? acc1[1] : acc1[0]) + rx;
        sx = o1 ? acc1[2] : acc1[3]; rx = __shfl_xor_sync(F, sx, 1);
        float v23b = (o1 ? acc1[3] : acc1[2]) + rx;

        sx = o2 ? v01a : v23a; rx = __shfl_xor_sync(F, sx, 2);
        float ua = (o2 ? v23a : v01a) + rx;
        sx = o2 ? v01b : v23b; rx = __shfl_xor_sync(F, sx, 2);
        float ub = (o2 ? v23b : v01b) + rx;

        sx = o4 ? ua : ub; rx = __shfl_xor_sync(F, sx, 4);
        float w = (o4 ? ub : ua) + rx;
        w += __shfl_xor_sync(F, w, 8);
        w += __shfl_xor_sync(F, w, 16);

        if (lane < 8)
            sc[(lane & 3) * MM + t * TILE_M + wrp * 2 + ((lane >> 2) & 1)] += w;

        __syncwarp();
        if (lane == 0) MB_ARRIVE(ea);

        if (tid == 0 && t + NBUF < NT) {
            mbar_wait(ea, par);
            MB_EXPECT_TX(fa, TILE_BYTES);
            BULK_G2S(bufa + s * TILE_BYTES, src + (size_t)(t + NBUF) * TILE_BYTES,
                     (uint32_t)TILE_BYTES, fa);
        }

        if (++s == NBUF) { s = 0; par ^= 1; }
    }
    __syncthreads();

    const int h = tid >> 6;
    const int t = tid & 63;

    float mx = -1e30f;
    for (int m = t; m < MM; m += 64) mx = fmaxf(mx, sc[h * MM + m]);
    #pragma unroll
    for (int d = 16; d; d >>= 1) mx = fmaxf(mx, __shfl_xor_sync(0xffffffffu, mx, d));
    if (lane == 0) red[wrp] = mx;
    __syncthreads();
    const float hmax = fmaxf(red[h * 2], red[h * 2 + 1]);

    float sum = 0.f;
    for (int m = t; m < MM; m += 64) {
        float e = __expf(sc[h * MM + m] - hmax);
        sc[h * MM + m] = e;
        sum += e;
    }
    #pragma unroll
    for (int d = 16; d; d >>= 1) sum += __shfl_xor_sync(0xffffffffu, sum, d);
    __syncthreads();
    if (lane == 0) red[wrp] = sum;
    __syncthreads();
    const float inv = 1.0f / (red[h * 2] + red[h * 2 + 1]);

    float* ao = attn_out + ((size_t)h * NN + n) * MM;
    for (int m = t; m < MM; m += 64) ao[m] = sc[h * MM + m] * inv;
}

// ============================================================
// K5: hidden = attn @ v, per-head 64x64 GEMM tile + m-split 4.
// grid (12, 4, 4) = 192 blocks, 256 threads.
// All 3 m-phases (64 m each) prefetched via cp.async into 96 KB
// triple-buffered dynamic smem; 4n x 4c register tile per thread;
// partial results combined with atomicAdd (hidden zeroed in qkv).
// ============================================================
__global__ __launch_bounds__(256) void av_kernel(const float* __restrict__ attn_g,
                                                 float* __restrict__ out_h)
{
    extern __shared__ __align__(16) float avs[];
    const int n0  = blockIdx.x * 64;
    const int h   = blockIdx.y;
    const int mb0 = blockIdx.z * 192;
    const int tid = threadIdx.x;
    const int tx  = tid & 15;        // c4 group: c = tx*4
    const int ty  = tid >> 4;        // n group: rows ty*4..ty*4+3

    // issue all 3 phase loads up-front (3 commit groups)
    #pragma unroll
    for (int ph = 0; ph < 3; ph++) {
        float* a_p = avs + ph * AV_PHASE_FLOATS;          // [64 n][64 m]
        float* v_p = a_p + 64 * 64;                        // [64 m][64 c]
        const int m0 = mb0 + ph * 64;
        #pragma unroll
        for (int i = tid; i < 1024; i += 256) {
            int r = i >> 4, ch = i & 15;                   // row, 16B chunk
            cp_async16(a_p + r * 64 + ch * 4,
                       attn_g + ((size_t)h * NN + n0 + r) * MM + m0 + ch * 4);
            cp_async16(v_p + r * 64 + ch * 4,
                       g_v + (size_t)(m0 + r) * DM + h * 64 + ch * 4);
        }
        CP_COMMIT();
    }

    float4 acc[4];
    #pragma unroll
    for (int i = 0; i < 4; i++) acc[i] = make_float4(0.f, 0.f, 0.f, 0.f);

    #pragma unroll
    for (int ph = 0; ph < 3; ph++) {
        if (ph == 0) CP_WAIT(2);
        else if (ph == 1) CP_WAIT(1);
        else CP_WAIT(0);
        __syncthreads();

        const float* a_p = avs + ph * AV_PHASE_FLOATS;
        const float* v_p = a_p + 64 * 64;

        #pragma unroll 4
        for (int mm = 0; mm < 64; mm += 4) {
            float4 a0 = *(const float4*)&a_p[(ty * 4 + 0) * 64 + mm];
            float4 a1 = *(const float4*)&a_p[(ty * 4 + 1) * 64 + mm];
            float4 a2 = *(const float4*)&a_p[(ty * 4 + 2) * 64 + mm];
            float4 a3 = *(const float4*)&a_p[(ty * 4 + 3) * 64 + mm];
            float4 v0 = *(const float4*)&v_p[(mm + 0) * 64 + tx * 4];
            float4 v1 = *(const float4*)&v_p[(mm + 1) * 64 + tx * 4];
            float4 v2 = *(const float4*)&v_p[(mm + 2) * 64 + tx * 4];
            float4 v3 = *(const float4*)&v_p[(mm + 3) * 64 + tx * 4];

            acc[0].x += a0.x*v0.x + a0.y*v1.x + a0.z*v2.x + a0.w*v3.x;
            acc[0].y += a0.x*v0.y + a0.y*v1.y + a0.z*v2.y + a0.w*v3.y;
            acc[0].z += a0.x*v0.z + a0.y*v1.z + a0.z*v2.z + a0.w*v3.z;
            acc[0].w += a0.x*v0.w + a0.y*v1.w + a0.z*v2.w + a0.w*v3.w;
            acc[1].x += a1.x*v0.x + a1.y*v1.x + a1.z*v2.x + a1.w*v3.x;
            acc[1].y += a1.x*v0.y + a1.y*v1.y + a1.z*v2.y + a1.w*v3.y;
            acc[1].z += a1.x*v0.z + a1.y*v1.z + a1.z*v2.z + a1.w*v3.z;
            acc[1].w += a1.x*v0.w + a1.y*v1.w + a1.z*v2.w + a1.w*v3.w;
            acc[2].x += a2.x*v0.x + a2.y*v1.x + a2.z*v2.x + a2.w*v3.x;
            acc[2].y += a2.x*v0.y + a2.y*v1.y + a2.z*v2.y + a2.w*v3.y;
            acc[2].z += a2.x*v0.z + a2.y*v1.z + a2.z*v2.z + a2.w*v3.z;
            acc[2].w += a2.x*v0.w + a2.y*v1.w + a2.z*v2.w + a2.w*v3.w;
            acc[3].x += a3.x*v0.x + a3.y*v1.x + a3.z*v2.x + a3.w*v3.x;
            acc[3].y += a3.x*v0.y + a3.y*v1.y + a3.z*v2.y + a3.w*v3.y;
            acc[3].z += a3.x*v0.z + a3.y*v1.z + a3.z*v2.z + a3.w*v3.z;
            acc[3].w += a3.x*v0.w + a3.y*v1.w + a3.z*v2.w + a3.w*v3.w;
        }
    }

    #pragma unroll
    for (int i = 0; i < 4; i++) {
        float* dst = out_h + (size_t)(n0 + ty * 4 + i) * DM + h * 64 + tx * 4;
        atomicAdd(dst + 0, acc[i].x);
        atomicAdd(dst + 1, acc[i].y);
        atomicAdd(dst + 2, acc[i].z);
        atomicAdd(dst + 3, acc[i].w);
    }
}

// ============================================================
// launch
// ============================================================
extern "C" void kernel_launch(void* const* d_in, const int* in_sizes, int n_in,
                              void* d_out, int out_size)
{
    const float* in_q = (const float*)d_in[0];
    const float* in_k = (const float*)d_in[1];
    const float* in_v = (const float*)d_in[2];
    const float* emb  = (const float*)d_in[3];
    const float* Wq   = (const float*)d_in[4];
    const float* bq   = (const float*)d_in[5];
    const float* Wk   = (const float*)d_in[6];
    const float* bk   = (const float*)d_in[7];
    const float* Wv   = (const float*)d_in[8];
    const float* bv   = (const float*)d_in[9];
    const float* Wp   = (const float*)d_in[10];
    const float* bp   = (const float*)d_in[11];

    float* out      = (float*)d_out;
    float* out_attn = out + NN * DM;   // hidden (196608) then attn (2359296)

    static bool attr_set = false;
    if (!attr_set) {
        cudaFuncSetAttribute(attn_kernel, cudaFuncAttributeMaxDynamicSharedMemorySize,
                             DYN_SMEM_BYTES);
        cudaFuncSetAttribute(av_kernel, cudaFuncAttributeMaxDynamicSharedMemorySize,
                             AV_DYN_BYTES);
        attr_set = true;
    }

    qkv_kernel<<<dim3(NN / 16, 3), 256>>>(in_q, in_k, in_v, Wq, bq, Wk, bk, Wv, bv, Wp, bp, out);
    se_kernel<<<dim3(MM / 64, NN / 64, NH), 256>>>();
    attn_kernel<<<NN, 256, DYN_SMEM_BYTES>>>(emb, out_attn);
    av_kernel<<<dim3(12, NH, 4), 256, AV_DYN_BYTES>>>(out_attn, out);
}

// round 10
// speedup vs baseline: 1.3456x; 1.3456x over previous
#include <cuda_runtime.h>
#include <math.h>
#include <stdint.h>

#define DM 256
#define NH 4
#define HD 64
#define NN 768
#define MM 768

#define TILE_M 16
#define NBUF 3
#define NT (MM / TILE_M)              // 48 tiles
#define TILE_BYTES (TILE_M * DM * 4)  // 16384
#define TILE_FLOATS (TILE_M * DM)     // 4096
#define DYN_SMEM_BYTES ((NH * MM + NBUF * TILE_FLOATS) * 4)   // 61440

// av kernel: per phase, attn[16][64] + v[64][64]; 3-deep ring
#define AV_CH 64
#define AV_PH (MM / AV_CH)                       // 12 phases
#define AV_BUF_FLOATS (16 * AV_CH + AV_CH * 64)  // 5120
#define AV_DYN_BYTES (3 * AV_BUF_FLOATS * 4)     // 61440

// ---- scratch (static device globals: allocation-free) ----
__device__ float g_q[NN * DM];
__device__ float g_k[NN * DM];            // k' = 0.125*(xk@Wk.T + bk + bp)
__device__ float g_v[NN * DM];
__device__ float g_R[NN * NH * DM];       // R[n][h][e] = 0.125 * q_h[n] @ Wp_h
__device__ float g_Se[NH * NN * MM];      // q·k' (scaled, bp folded)

// ---- mbarrier / bulk-copy / cp.async PTX helpers ----
__device__ __forceinline__ uint32_t smem_u32(const void* p) {
    return (uint32_t)__cvta_generic_to_shared(p);
}
#define MB_INIT(addr, cnt) \
    asm volatile("mbarrier.init.shared.b64 [%0], %1;" :: "r"(addr), "r"(cnt) : "memory")
#define MB_EXPECT_TX(addr, bytes) \
    asm volatile("mbarrier.arrive.expect_tx.shared.b64 _, [%0], %1;" :: "r"(addr), "r"(bytes) : "memory")
#define MB_ARRIVE(addr) \
    asm volatile("mbarrier.arrive.shared.b64 _, [%0];" :: "r"(addr) : "memory")
#define BULK_G2S(dst, src, bytes, mbar_) \
    asm volatile("cp.async.bulk.shared::cluster.global.mbarrier::complete_tx::bytes [%0], [%1], %2, [%3];" \
                 :: "r"(dst), "l"(src), "r"(bytes), "r"(mbar_) : "memory")

__device__ __forceinline__ void mbar_wait(uint32_t addr, uint32_t parity) {
    asm volatile(
        "{\n\t"
        ".reg .pred P;\n\t"
        "WL%=:\n\t"
        "mbarrier.try_wait.parity.acquire.cta.shared::cta.b64 P, [%0], %1, 0x989680;\n\t"
        "@P bra WD%=;\n\t"
        "bra WL%=;\n\t"
        "WD%=:\n\t"
        "}"
        :: "r"(addr), "r"(parity) : "memory");
}

__device__ __forceinline__ void cp_async16(float* dst, const float* src) {
    asm volatile("cp.async.ca.shared.global [%0], [%1], 16;"
                 :: "r"(smem_u32(dst)), "l"(src) : "memory");
}
#define CP_COMMIT() asm volatile("cp.async.commit_group;" ::: "memory")
#define CP_WAIT(n)  asm volatile("cp.async.wait_group %0;" :: "n"(n) : "memory")

// ============================================================
// K1: q/k'/v projections.  grid (48, 3), 256 threads.  (R6 version)
// ============================================================
__global__ __launch_bounds__(256) void qkv_kernel(
    const float* __restrict__ in_q, const float* __restrict__ in_k, const float* __restrict__ in_v,
    const float* __restrict__ Wq, const float* __restrict__ bq,
    const float* __restrict__ Wk, const float* __restrict__ bk,
    const float* __restrict__ Wv, const float* __restrict__ bv,
    const float* __restrict__ bp)
{
    const int z  = blockIdx.y;
    const int n0 = blockIdx.x * 16;
    const int d  = threadIdx.x;

    const float* x = (z == 0) ? in_q : ((z == 1) ? in_k : in_v);
    const float* W = (z == 0) ? Wq   : ((z == 1) ? Wk   : Wv);
    float bias     = (z == 0) ? bq[d] : ((z == 1) ? (bk[d] + bp[d]) : bv[d]);
    const float scale = (z == 1) ? 0.125f : 1.0f;
    float* out = (z == 0) ? g_q : ((z == 1) ? g_k : g_v);

    __shared__ float xs[256 * 20];
    for (int idx = d; idx < 16 * 256; idx += 256) {
        int ni = idx >> 8, e = idx & 255;
        xs[e * 20 + ni] = x[(n0 + ni) * DM + e];
    }
    __syncthreads();

    float4 acc[4];
    #pragma unroll
    for (int g = 0; g < 4; g++) acc[g] = make_float4(0.f, 0.f, 0.f, 0.f);

    const float4* Wr = (const float4*)(W + d * DM);
    #pragma unroll 4
    for (int e4 = 0; e4 < 64; e4++) {
        float4 wv = Wr[e4];
        float wa[4] = {wv.x, wv.y, wv.z, wv.w};
        #pragma unroll
        for (int k = 0; k < 4; k++) {
            int e = e4 * 4 + k;
            float w = wa[k];
            #pragma unroll
            for (int g = 0; g < 4; g++) {
                float4 xf = *(const float4*)&xs[e * 20 + g * 4];
                acc[g].x += xf.x * w;
                acc[g].y += xf.y * w;
                acc[g].z += xf.z * w;
                acc[g].w += xf.w * w;
            }
        }
    }
    #pragma unroll
    for (int g = 0; g < 4; g++) {
        out[(n0 + g * 4 + 0) * DM + d] = scale * (acc[g].x + bias);
        out[(n0 + g * 4 + 1) * DM + d] = scale * (acc[g].y + bias);
        out[(n0 + g * 4 + 2) * DM + d] = scale * (acc[g].z + bias);
        out[(n0 + g * 4 + 3) * DM + d] = scale * (acc[g].w + bias);
    }
}

// ============================================================
// K2: R projection.  grid (48, 4), 256 threads.  (R6 version)
// ============================================================
__global__ __launch_bounds__(256) void rproj_kernel(const float* __restrict__ Wp)
{
    const int n0 = blockIdx.x * 16;
    const int h  = blockIdx.y;
    const int e  = threadIdx.x;

    __shared__ float qs[64 * 20];
    for (int idx = e; idx < 16 * 64; idx += 256) {
        int ni = idx >> 6, c = idx & 63;
        qs[c * 20 + ni] = g_q[(n0 + ni) * DM + h * 64 + c];
    }
    __syncthreads();

    float4 acc[4];
    #pragma unroll
    for (int g = 0; g < 4; g++) acc[g] = make_float4(0.f, 0.f, 0.f, 0.f);

    #pragma unroll 4
    for (int c = 0; c < 64; c++) {
        float w = Wp[(h * 64 + c) * DM + e];
        #pragma unroll
        for (int g = 0; g < 4; g++) {
            float4 xf = *(const float4*)&qs[c * 20 + g * 4];
            acc[g].x += xf.x * w;
            acc[g].y += xf.y * w;
            acc[g].z += xf.z * w;
            acc[g].w += xf.w * w;
        }
    }
    #pragma unroll
    for (int g = 0; g < 4; g++) {
        g_R[(n0 + g * 4 + 0) * (NH * DM) + h * DM + e] = 0.125f * acc[g].x;
        g_R[(n0 + g * 4 + 1) * (NH * DM) + h * DM + e] = 0.125f * acc[g].y;
        g_R[(n0 + g * 4 + 2) * (NH * DM) + h * DM + e] = 0.125f * acc[g].z;
        g_R[(n0 + g * 4 + 3) * (NH * DM) + h * DM + e] = 0.125f * acc[g].w;
    }
}

// ============================================================
// K3: Se[h][n][m] = q_h[n] · k'_h[m].   grid (12, 12, 4), 256 threads.
// ============================================================
__global__ __launch_bounds__(256) void se_kernel()
{
    const int m0 = blockIdx.x * 64;
    const int n0 = blockIdx.y * 64;
    const int h  = blockIdx.z;
    const int tid = threadIdx.x;

    __shared__ float qs[64 * 68];
    __shared__ float ks[64 * 68];
    for (int idx = tid; idx < 64 * 64; idx += 256) {
        int i = idx >> 6, c = idx & 63;
        qs[c * 68 + i] = g_q[(n0 + i) * DM + h * 64 + c];
        ks[c * 68 + i] = g_k[(m0 + i) * DM + h * 64 + c];
    }
    __syncthreads();

    const int tx = tid & 15, ty = tid >> 4;
    float acc[4][4];
    #pragma unroll
    for (int i = 0; i < 4; i++)
        #pragma unroll
        for (int j = 0; j < 4; j++) acc[i][j] = 0.f;

    #pragma unroll 4
    for (int c = 0; c < 64; c++) {
        float4 a = *(const float4*)&qs[c * 68 + ty * 4];
        float4 b = *(const float4*)&ks[c * 68 + tx * 4];
        float av[4] = {a.x, a.y, a.z, a.w};
        float bv[4] = {b.x, b.y, b.z, b.w};
        #pragma unroll
        for (int i = 0; i < 4; i++)
            #pragma unroll
            for (int j = 0; j < 4; j++) acc[i][j] += av[i] * bv[j];
    }
    #pragma unroll
    for (int i = 0; i < 4; i++) {
        float4 r = make_float4(acc[i][0], acc[i][1], acc[i][2], acc[i][3]);
        *(float4*)&g_Se[((size_t)h * NN + (n0 + ty * 4 + i)) * MM + m0 + tx * 4] = r;
    }
}

// ============================================================
// K4: fused RPE-score + softmax, depth-3 bulk-copy pipeline. (unchanged)
// ============================================================
__global__ __launch_bounds__(256, 3) void attn_kernel(const float* __restrict__ emb,
                                                      float* __restrict__ attn_out)
{
    extern __shared__ __align__(16) float dyn[];
    float* sc  = dyn;                 // NH*MM floats (12 KB)
    float* buf = dyn + NH * MM;       // NBUF * 4096 floats (48 KB)

    const int n    = blockIdx.x;
    const int tid  = threadIdx.x;
    const int lane = tid & 31;
    const int wrp  = tid >> 5;

    __shared__ __align__(8) unsigned long long mbar[2 * NBUF];
    __shared__ float red[8];

    const uint32_t mb   = smem_u32(mbar);
    const uint32_t bufa = smem_u32(buf);

    if (tid == 0) {
        #pragma unroll
        for (int i = 0; i < NBUF; i++) {
            MB_INIT(mb + i * 8, 1);
            MB_INIT(mb + (NBUF + i) * 8, 8);
        }
    }

    #pragma unroll
    for (int h = 0; h < NH; h++)
        for (int m = tid; m < MM; m += 256)
            sc[h * MM + m] = g_Se[((size_t)h * NN + n) * MM + m];

    const float4* Rr = (const float4*)(g_R + (size_t)n * NH * DM);
    float4 rA[NH], rB[NH];
    #pragma unroll
    for (int h = 0; h < NH; h++) {
        rA[h] = Rr[h * 64 + lane];
        rB[h] = Rr[h * 64 + 32 + lane];
    }
    __syncthreads();

    const char* src = (const char*)(emb + (size_t)n * MM * DM);
    if (tid == 0) {
        #pragma unroll
        for (int i = 0; i < NBUF; i++) {
            MB_EXPECT_TX(mb + i * 8, TILE_BYTES);
            BULK_G2S(bufa + i * TILE_BYTES, src + (size_t)i * TILE_BYTES,
                     (uint32_t)TILE_BYTES, mb + i * 8);
        }
    }

    const unsigned F = 0xffffffffu;
    const bool o1 = lane & 1, o2 = lane & 2, o4 = lane & 4;

    int s = 0;
    uint32_t par = 0;
    for (int t = 0; t < NT; t++) {
        const uint32_t fa = mb + s * 8;
        const uint32_t ea = mb + (NBUF + s) * 8;

        mbar_wait(fa, par);

        const float* bufp = buf + s * TILE_FLOATS;
        const float4* r0p = (const float4*)(bufp + (wrp * 2) * DM);
        const float4* r1p = (const float4*)(bufp + (wrp * 2 + 1) * DM);
        float4 a0 = r0p[lane], a1 = r0p[32 + lane];
        float4 b0 = r1p[lane], b1 = r1p[32 + lane];

        float acc0[NH], acc1[NH];
        #pragma unroll
        for (int h = 0; h < NH; h++) {
            acc0[h] = a0.x * rA[h].x + a0.y * rA[h].y + a0.z * rA[h].z + a0.w * rA[h].w
                    + a1.x * rB[h].x + a1.y * rB[h].y + a1.z * rB[h].z + a1.w * rB[h].w;
            acc1[h] = b0.x * rA[h].x + b0.y * rA[h].y + b0.z * rA[h].z + b0.w * rA[h].w
                    + b1.x * rB[h].x + b1.y * rB[h].y + b1.z * rB[h].z + b1.w * rB[h].w;
        }

        float sx, rx;
        sx = o1 ? acc0[0] : acc0[1]; rx = __shfl_xor_sync(F, sx, 1);
        float v01a = (o1 ? acc0[1] : acc0[0]) + rx;
        sx = o1 ? acc0[2] : acc0[3]; rx = __shfl_xor_sync(F, sx, 1);
        float v23a = (o1 ? acc0[3] : acc0[2]) + rx;
        sx = o1 ? acc1[0] : acc1[1]; rx = __shfl_xor_sync(F, sx, 1);
        float v01b = (o1 ? acc1[1] : acc1[0]) + rx;
        sx = o1 ? acc1[2] : acc1[3]; rx = __shfl_xor_sync(F, sx, 1);
        float v23b = (o1 ? acc1[3] : acc1[2]) + rx;

        sx = o2 ? v01a : v23a; rx = __shfl_xor_sync(F, sx, 2);
        float ua = (o2 ? v23a : v01a) + rx;
        sx = o2 ? v01b : v23b; rx = __shfl_xor_sync(F, sx, 2);
        float ub = (o2 ? v23b : v01b) + rx;

        sx = o4 ? ua : ub; rx = __shfl_xor_sync(F, sx, 4);
        float w = (o4 ? ub : ua) + rx;
        w += __shfl_xor_sync(F, w, 8);
        w += __shfl_xor_sync(F, w, 16);

        if (lane < 8)
            sc[(lane & 3) * MM + t * TILE_M + wrp * 2 + ((lane >> 2) & 1)] += w;

        __syncwarp();
        if (lane == 0) MB_ARRIVE(ea);

        if (tid == 0 && t + NBUF < NT) {
            mbar_wait(ea, par);
            MB_EXPECT_TX(fa, TILE_BYTES);
            BULK_G2S(bufa + s * TILE_BYTES, src + (size_t)(t + NBUF) * TILE_BYTES,
                     (uint32_t)TILE_BYTES, fa);
        }

        if (++s == NBUF) { s = 0; par ^= 1; }
    }
    __syncthreads();

    const int h = tid >> 6;
    const int t = tid & 63;

    float mx = -1e30f;
    for (int m = t; m < MM; m += 64) mx = fmaxf(mx, sc[h * MM + m]);
    #pragma unroll
    for (int d = 16; d; d >>= 1) mx = fmaxf(mx, __shfl_xor_sync(0xffffffffu, mx, d));
    if (lane == 0) red[wrp] = mx;
    __syncthreads();
    const float hmax = fmaxf(red[h * 2], red[h * 2 + 1]);

    float sum = 0.f;
    for (int m = t; m < MM; m += 64) {
        float e = __expf(sc[h * MM + m] - hmax);
        sc[h * MM + m] = e;
        sum += e;
    }
    #pragma unroll
    for (int d = 16; d; d >>= 1) sum += __shfl_xor_sync(0xffffffffu, sum, d);
    __syncthreads();
    if (lane == 0) red[wrp] = sum;
    __syncthreads();
    const float inv = 1.0f / (red[h * 2] + red[h * 2 + 1]);

    float* ao = attn_out + ((size_t)h * NN + n) * MM;
    for (int m = t; m < MM; m += 64) ao[m] = sc[h * MM + m] * inv;
}

// ============================================================
// K5: hidden = attn @ v.  grid (48, 4), 256 threads, 3 CTAs/SM.
// Block: 16n x 64c (one head), m in 12 x 64 chunks through a
// 3-deep cp.async ring (60 KB dynamic smem). Direct stores,
// no atomics, no zero-init, each output written exactly once.
// ============================================================
__global__ __launch_bounds__(256, 3) void av_kernel(const float* __restrict__ attn_g,
                                                    float* __restrict__ out_h)
{
    extern __shared__ __align__(16) float avs[];
    const int n0  = blockIdx.x * 16;
    const int h   = blockIdx.y;
    const int tid = threadIdx.x;
    const int nl  = tid >> 4;        // output row 0..15
    const int c4  = tid & 15;        // float4 column group

    // stage issue: attn[16][64] (256 float4) + v[64][64] (1024 float4)
    auto issue = [&](int ph, int sb) {
        float* a_p = avs + sb * AV_BUF_FLOATS;
        float* v_p = a_p + 16 * AV_CH;
        const int m0 = ph * AV_CH;
        {   // attn rows: i in [0,256): r = i>>4, ch = i&15
            int r = tid >> 4, ch = tid & 15;
            cp_async16(a_p + r * 64 + ch * 4,
                       attn_g + ((size_t)h * NN + n0 + r) * MM + m0 + ch * 4);
        }
        #pragma unroll
        for (int i = 0; i < 4; i++) {
            int j = tid + i * 256;
            int r = j >> 4, ch = j & 15;
            cp_async16(v_p + r * 64 + ch * 4,
                       g_v + (size_t)(m0 + r) * DM + h * 64 + ch * 4);
        }
        CP_COMMIT();
    };

    issue(0, 0);
    issue(1, 1);

    float4 acc = make_float4(0.f, 0.f, 0.f, 0.f);

    for (int ph = 0; ph < AV_PH; ph++) {
        const int sb = ph % 3;

        __syncthreads();   // all threads done with buffer (ph+2)%3 (iter ph-1)
        if (ph + 2 < AV_PH) {
            issue(ph + 2, (ph + 2) % 3);
            CP_WAIT(2);
        } else if (ph + 1 < AV_PH) {
            CP_WAIT(1);
        } else {
            CP_WAIT(0);
        }
        __syncthreads();   // phase ph data visible

        const float* a_p = avs + sb * AV_BUF_FLOATS;
        const float* v_p = a_p + 16 * AV_CH;

        #pragma unroll
        for (int mm = 0; mm < AV_CH; mm += 4) {
            float4 a4 = *(const float4*)&a_p[nl * 64 + mm];
            float4 v0 = *(const float4*)&v_p[(mm + 0) * 64 + c4 * 4];
            float4 v1 = *(const float4*)&v_p[(mm + 1) * 64 + c4 * 4];
            float4 v2 = *(const float4*)&v_p[(mm + 2) * 64 + c4 * 4];
            float4 v3 = *(const float4*)&v_p[(mm + 3) * 64 + c4 * 4];
            acc.x += a4.x * v0.x + a4.y * v1.x + a4.z * v2.x + a4.w * v3.x;
            acc.y += a4.x * v0.y + a4.y * v1.y + a4.z * v2.y + a4.w * v3.y;
            acc.z += a4.x * v0.z + a4.y * v1.z + a4.z * v2.z + a4.w * v3.z;
            acc.w += a4.x * v0.w + a4.y * v1.w + a4.z * v2.w + a4.w * v3.w;
        }
    }

    *(float4*)(out_h + (size_t)(n0 + nl) * DM + h * 64 + c4 * 4) = acc;
}

// ============================================================
// launch
// ============================================================
extern "C" void kernel_launch(void* const* d_in, const int* in_sizes, int n_in,
                              void* d_out, int out_size)
{
    const float* in_q = (const float*)d_in[0];
    const float* in_k = (const float*)d_in[1];
    const float* in_v = (const float*)d_in[2];
    const float* emb  = (const float*)d_in[3];
    const float* Wq   = (const float*)d_in[4];
    const float* bq   = (const float*)d_in[5];
    const float* Wk   = (const float*)d_in[6];
    const float* bk   = (const float*)d_in[7];
    const float* Wv   = (const float*)d_in[8];
    const float* bv   = (const float*)d_in[9];
    const float* Wp   = (const float*)d_in[10];
    const float* bp   = (const float*)d_in[11];

    float* out      = (float*)d_out;
    float* out_attn = out + NN * DM;   // hidden (196608) then attn (2359296)

    static bool attr_set = false;
    if (!attr_set) {
        cudaFuncSetAttribute(attn_kernel, cudaFuncAttributeMaxDynamicSharedMemorySize,
                             DYN_SMEM_BYTES);
        cudaFuncSetAttribute(av_kernel, cudaFuncAttributeMaxDynamicSharedMemorySize,
                             AV_DYN_BYTES);
        attr_set = true;
    }

    qkv_kernel<<<dim3(NN / 16, 3), 256>>>(in_q, in_k, in_v, Wq, bq, Wk, bk, Wv, bv, bp);
    rproj_kernel<<<dim3(NN / 16, NH), 256>>>(Wp);
    se_kernel<<<dim3(MM / 64, NN / 64, NH), 256>>>();
    attn_kernel<<<NN, 256, DYN_SMEM_BYTES>>>(emb, out_attn);
    av_kernel<<<dim3(NN / 16, NH), 256, AV_DYN_BYTES>>>(out_attn, out);
}